// round 8
// baseline (speedup 1.0000x reference)
#include <cuda_runtime.h>
#include <cuda_fp16.h>
#include <stdint.h>

// EdgeHead via warp-level mma.sync (HMMA fp16) + packed f32x2 scalar math.
// out[e] = relu(LN([u,v,|u-v|,u*v]) @ (gamma.*W1) + bc) @ W2 + b2,
// bc = beta @ W1 + b1 (LN affine folded into weights).
// A fragments built in registers; LDG.128 gathers via k-axis permutation
// (B stored with the same permutation). LN stats + normalization use
// fma/add/mul.rn.f32x2 (FFMA2) to halve fp32 instruction count.

#define NTHREADS 128
typedef unsigned long long u64;

__device__ __forceinline__ u64 pk2(float x, float y) {
    u64 r; asm("mov.b64 %0, {%1, %2};" : "=l"(r) : "f"(x), "f"(y)); return r;
}
__device__ __forceinline__ void upk2(u64 a, float& x, float& y) {
    asm("mov.b64 {%0, %1}, %2;" : "=f"(x), "=f"(y) : "l"(a));
}
__device__ __forceinline__ u64 fma2(u64 a, u64 b, u64 c) {
    u64 r; asm("fma.rn.f32x2 %0, %1, %2, %3;" : "=l"(r) : "l"(a), "l"(b), "l"(c));
    return r;
}
__device__ __forceinline__ u64 add2(u64 a, u64 b) {
    u64 r; asm("add.rn.f32x2 %0, %1, %2;" : "=l"(r) : "l"(a), "l"(b)); return r;
}
__device__ __forceinline__ u64 mul2(u64 a, u64 b) {
    u64 r; asm("mul.rn.f32x2 %0, %1, %2;" : "=l"(r) : "l"(a), "l"(b)); return r;
}
#define ABS2MASK 0x7fffffff7fffffffULL

__device__ __forceinline__ uint32_t pack_h2(float x, float y) {
    __half2 t = __floats2half2_rn(x, y);   // .x = low half
    uint32_t r; memcpy(&r, &t, 4); return r;
}
// half2 from packed f32x2
__device__ __forceinline__ uint32_t h2_from2(u64 z) {
    float x, y; upk2(z, x, y); return pack_h2(x, y);
}

__device__ __forceinline__ void mma16816(float* c, const uint32_t* a,
                                         uint32_t b0, uint32_t b1) {
    asm volatile(
        "mma.sync.aligned.m16n8k16.row.col.f32.f16.f16.f32 "
        "{%0,%1,%2,%3}, {%4,%5,%6,%7}, {%8,%9}, {%0,%1,%2,%3};"
        : "+f"(c[0]), "+f"(c[1]), "+f"(c[2]), "+f"(c[3])
        : "r"(a[0]), "r"(a[1]), "r"(a[2]), "r"(a[3]), "r"(b0), "r"(b1));
}

__device__ __forceinline__ void ldsm4(uint32_t addr, uint32_t& r0, uint32_t& r1,
                                      uint32_t& r2, uint32_t& r3) {
    asm volatile("ldmatrix.sync.aligned.m8n8.x4.shared.b16 {%0,%1,%2,%3}, [%4];"
                 : "=r"(r0), "=r"(r1), "=r"(r2), "=r"(r3) : "r"(addr));
}

// packed z for feature segment s (compile-time): z = feat*rs + nm
__device__ __forceinline__ u64 zval2(int s, u64 uu, u64 vv, u64 rs2, u64 nm2,
                                     u64 neg1) {
    if (s == 0) return fma2(uu, rs2, nm2);
    if (s == 1) return fma2(vv, rs2, nm2);
    if (s == 2) {
        u64 d = fma2(vv, neg1, uu) & ABS2MASK;
        return fma2(d, rs2, nm2);
    }
    return fma2(mul2(uu, vv), rs2, nm2);
}

__global__ __launch_bounds__(NTHREADS, 4)
void edgehead_mma(const float* __restrict__ h,
                  const void* __restrict__ ep_raw,
                  const float* __restrict__ gamma,
                  const float* __restrict__ beta,
                  const float* __restrict__ W1,
                  const float* __restrict__ b1,
                  const float* __restrict__ W2,
                  const float* __restrict__ b2,
                  float* __restrict__ out,
                  int E, int nGroups)
{
    __shared__ __align__(128) unsigned char Bhi[16384];  // 32j x 256k fp16, swz
    __shared__ float bc_s[32], w2_s[32];

    const int tid = threadIdx.x;
    const int wid = tid >> 5;
    const int lane = tid & 31;

    // ---- stage B^T = (gamma .* W1)^T fp16, k-permuted + XOR-swizzled ----
    // phys k within 16-block maps to mma col m = ((k&12)>>1) + ((k&2)?8:0)
    for (int p = tid; p < 4096; p += NTHREADS) {
        const int j = p & 31;
        const int k0 = (p >> 5) << 1;                    // even phys k
        const float w0 = gamma[k0] * W1[k0 * 32 + j];
        const float w1 = gamma[k0 + 1] * W1[(k0 + 1) * 32 + j];
        const int m0 = ((k0 & 12) >> 1) + ((k0 & 2) ? 8 : 0);
        const int kp = (k0 & ~15) + m0;                  // permuted, even
        const uint32_t off = (uint32_t)(j * 512 + ((((kp >> 3)) ^ (j & 7)) << 4)
                                        + (kp & 7) * 2);
        *(uint32_t*)(Bhi + off) = pack_h2(w0, w1);
    }
    if (tid < 32) {
        float acc = b1[tid];
        #pragma unroll 8
        for (int k = 0; k < 256; k++) acc = fmaf(beta[k], W1[k * 32 + tid], acc);
        bc_s[tid] = acc;
        w2_s[tid] = W2[tid];
    }
    __syncthreads();

    // ---- edge index dtype sniff (int64 vs int32) ----
    const int* ep32 = (const int*)ep_raw;
    const long long* ep64 = (const long long*)ep_raw;
    int hiOr = 0;
    #pragma unroll
    for (int t = 1; t < 16; t += 2) hiOr |= ep32[t];
    const bool wide = (hiOr == 0);
    const float b2v = b2[0];
    const u64 neg1 = pk2(-1.f, -1.f);

    // ---- per-lane constants ----
    const int cq = lane & 3;           // quad position: owns phys dims 4cq..+3
    const int q = lane >> 2;           // edge row within group (and +8)
    const float4* __restrict__ hv4 = (const float4*)h;   // 16 float4 per node

    // ldmatrix lane addressing: x4 = matrices (n0,k0)(n0,k1)(n1,k0)(n1,k1)
    const int x7 = lane & 7;
    const int pday = (lane >> 3) & 1;              // chunk parity this lane serves
    const int jrow = ((lane >> 4)) * 8 + x7;       // j for nbase=0
    const uint32_t bhiB = (uint32_t)__cvta_generic_to_shared(Bhi) + jrow * 512;

    const int gw = blockIdx.x * (NTHREADS / 32) + wid;
    const int gstride = gridDim.x * (NTHREADS / 32);

    for (int g = gw; g < nGroups; g += gstride) {
        const int e0 = g * 16 + q;
        const int e1 = e0 + 8;
        const bool v0 = e0 < E, v1 = e1 < E;
        int s0, d0, s1i, d1;
        if (wide) {
            s0 = v0 ? (int)ep64[e0] : 0; d0 = v0 ? (int)ep64[e0 + E] : 0;
            s1i = v1 ? (int)ep64[e1] : 0; d1 = v1 ? (int)ep64[e1 + E] : 0;
        } else {
            s0 = v0 ? ep32[e0] : 0; d0 = v0 ? ep32[e0 + E] : 0;
            s1i = v1 ? ep32[e1] : 0; d1 = v1 ? ep32[e1 + E] : 0;
        }

        // gather: lane owns phys dims {16t + 4cq .. +3}, one float4 per t
        float4 u0[4], v0r[4], u1[4], v1r[4];
        {
            const float4* pu0 = hv4 + (s0 * 16 + cq);
            const float4* pv0 = hv4 + (d0 * 16 + cq);
            const float4* pu1 = hv4 + (s1i * 16 + cq);
            const float4* pv1 = hv4 + (d1 * 16 + cq);
            #pragma unroll
            for (int t = 0; t < 4; t++) {
                u0[t]  = pu0[4 * t];
                v0r[t] = pv0[4 * t];
                u1[t]  = pu1[4 * t];
                v1r[t] = pv1[4 * t];
            }
        }

        // repack rows as f32x2 pairs: index 2t = (x,y), 2t+1 = (z,w)
        u64 U0[8], V0[8], U1[8], V1[8];
        #pragma unroll
        for (int t = 0; t < 4; t++) {
            U0[2*t]   = pk2(u0[t].x,  u0[t].y);
            U0[2*t+1] = pk2(u0[t].z,  u0[t].w);
            V0[2*t]   = pk2(v0r[t].x, v0r[t].y);
            V0[2*t+1] = pk2(v0r[t].z, v0r[t].w);
            U1[2*t]   = pk2(u1[t].x,  u1[t].y);
            U1[2*t+1] = pk2(u1[t].z,  u1[t].w);
            V1[2*t]   = pk2(v1r[t].x, v1r[t].y);
            V1[2*t+1] = pk2(v1r[t].z, v1r[t].w);
        }

        // LN stats per row, packed (quad reduce after)
        u64 S1a = 0, S2a = 0, S1b = 0, S2b = 0;   // 0.0,0.0 packed
        #pragma unroll
        for (int i = 0; i < 8; i++) {
            {
                const u64 uu = U0[i], vv = V0[i];
                const u64 p = mul2(uu, vv);
                const u64 d = fma2(vv, neg1, uu) & ABS2MASK;
                S1a = add2(S1a, add2(uu, vv));
                S1a = add2(S1a, add2(d, p));
                S2a = fma2(uu, uu, S2a); S2a = fma2(vv, vv, S2a);
                S2a = fma2(d, d, S2a);   S2a = fma2(p, p, S2a);
            }
            {
                const u64 uu = U1[i], vv = V1[i];
                const u64 p = mul2(uu, vv);
                const u64 d = fma2(vv, neg1, uu) & ABS2MASK;
                S1b = add2(S1b, add2(uu, vv));
                S1b = add2(S1b, add2(d, p));
                S2b = fma2(uu, uu, S2b); S2b = fma2(vv, vv, S2b);
                S2b = fma2(d, d, S2b);   S2b = fma2(p, p, S2b);
            }
        }
        float s1r0, s2r0, s1r1, s2r1, tx, ty;
        upk2(S1a, tx, ty); s1r0 = tx + ty;
        upk2(S2a, tx, ty); s2r0 = tx + ty;
        upk2(S1b, tx, ty); s1r1 = tx + ty;
        upk2(S2b, tx, ty); s2r1 = tx + ty;

        s1r0 += __shfl_xor_sync(0xffffffffu, s1r0, 1);
        s1r0 += __shfl_xor_sync(0xffffffffu, s1r0, 2);
        s2r0 += __shfl_xor_sync(0xffffffffu, s2r0, 1);
        s2r0 += __shfl_xor_sync(0xffffffffu, s2r0, 2);
        s1r1 += __shfl_xor_sync(0xffffffffu, s1r1, 1);
        s1r1 += __shfl_xor_sync(0xffffffffu, s1r1, 2);
        s2r1 += __shfl_xor_sync(0xffffffffu, s2r1, 1);
        s2r1 += __shfl_xor_sync(0xffffffffu, s2r1, 2);

        const float mu0 = s1r0 * (1.f / 256.f);
        const float rs0 = rsqrtf(fmaf(-mu0, mu0, s2r0 * (1.f / 256.f)) + 1e-5f);
        const float nm0 = -mu0 * rs0;
        const float mu1 = s1r1 * (1.f / 256.f);
        const float rs1 = rsqrtf(fmaf(-mu1, mu1, s2r1 * (1.f / 256.f)) + 1e-5f);
        const float nm1 = -mu1 * rs1;

        const u64 rs20 = pk2(rs0, rs0), nm20 = pk2(nm0, nm0);
        const u64 rs21 = pk2(rs1, rs1), nm21 = pk2(nm1, nm1);

        float acc[4][4];
        #pragma unroll
        for (int nt = 0; nt < 4; nt++)
            #pragma unroll
            for (int r = 0; r < 4; r++) acc[nt][r] = 0.f;

        // ---- 16 ksteps: packed z -> A frags, ldmatrix B, 4 mma ----
        // pair 2t -> mma k-lo (cols 2cq,2cq+1); 2t+1 -> k-hi (cols +8)
        #pragma unroll
        for (int ks = 0; ks < 16; ks++) {
            const int s = ks >> 2, t = ks & 3;
            uint32_t ah[4];
            ah[0] = h2_from2(zval2(s, U0[2*t],   V0[2*t],   rs20, nm20, neg1));
            ah[1] = h2_from2(zval2(s, U1[2*t],   V1[2*t],   rs21, nm21, neg1));
            ah[2] = h2_from2(zval2(s, U0[2*t+1], V0[2*t+1], rs20, nm20, neg1));
            ah[3] = h2_from2(zval2(s, U1[2*t+1], V1[2*t+1], rs21, nm21, neg1));

            const uint32_t sw = (uint32_t)((((ks * 2 + pday) ^ x7)) << 4);
            uint32_t bh[8];
            ldsm4(bhiB + sw,        bh[0], bh[1], bh[2], bh[3]);   // nt 0,1
            ldsm4(bhiB + sw + 8192, bh[4], bh[5], bh[6], bh[7]);   // nt 2,3

            #pragma unroll
            for (int nt = 0; nt < 4; nt++)
                mma16816(acc[nt], ah, bh[2 * nt], bh[2 * nt + 1]);
        }

        // ---- epilogue: relu + W2 dot (bc/w2 from smem), quad reduce ----
        const int c = cq * 2;
        float pp0 = 0.f, pp1 = 0.f;
        #pragma unroll
        for (int nt = 0; nt < 4; nt++) {
            const float bcx = bc_s[nt * 8 + c], bcy = bc_s[nt * 8 + c + 1];
            const float w2x = w2_s[nt * 8 + c], w2y = w2_s[nt * 8 + c + 1];
            pp0 = fmaf(fmaxf(acc[nt][0] + bcx, 0.f), w2x, pp0);
            pp0 = fmaf(fmaxf(acc[nt][1] + bcy, 0.f), w2y, pp0);
            pp1 = fmaf(fmaxf(acc[nt][2] + bcx, 0.f), w2x, pp1);
            pp1 = fmaf(fmaxf(acc[nt][3] + bcy, 0.f), w2y, pp1);
        }
        pp0 += __shfl_xor_sync(0xffffffffu, pp0, 1);
        pp0 += __shfl_xor_sync(0xffffffffu, pp0, 2);
        pp1 += __shfl_xor_sync(0xffffffffu, pp1, 1);
        pp1 += __shfl_xor_sync(0xffffffffu, pp1, 2);
        if (cq == 0) {
            if (v0) out[e0] = pp0 + b2v;
            if (v1) out[e1] = pp1 + b2v;
        }
    }
}

extern "C" void kernel_launch(void* const* d_in, const int* in_sizes, int n_in,
                              void* d_out, int out_size)
{
    const float* h     = (const float*)d_in[0];
    const void*  ep    = d_in[1];
    const float* gamma = (const float*)d_in[2];
    const float* beta  = (const float*)d_in[3];
    const float* W1    = (const float*)d_in[4];
    const float* b1    = (const float*)d_in[5];
    const float* W2    = (const float*)d_in[6];
    const float* b2    = (const float*)d_in[7];
    float* out = (float*)d_out;
    const int E = out_size;
    const int nGroups = (E + 15) / 16;

    int dev = 0, sms = 148;
    cudaGetDevice(&dev);
    cudaDeviceGetAttribute(&sms, cudaDevAttrMultiProcessorCount, dev);
    int grid = sms * 4;
    const int maxg = (nGroups + (NTHREADS / 32) - 1) / (NTHREADS / 32);
    if (grid > maxg) grid = maxg;

    edgehead_mma<<<grid, NTHREADS>>>(h, ep, gamma, beta, W1, b1, W2, b2,
                                     out, E, nGroups);
}